// round 7
// baseline (speedup 1.0000x reference)
#include <cuda_runtime.h>

// out[b, oz, oy, ox] = in[b*3137*768 + (1 + n*196 + g1*14 + g2)*768 + ch]
//   z = floor(oz*9/4)   -> n = z/9, c0 = z%9
//   y = floor(oy*63/32) -> g1 = y/9, c1 = y%9
//   x = floor(ox*63/32) -> g2 = x/9, c2 = x%9
//   ch = floor(float32(c0*81 + c1*9 + c2) * float32(768.0/729.0))  (bit-exact JAX)
//
// Final form: direct gather at the measured HBM floor (~386 MB @ ~6.5 TB/s).
// Thread = 4 consecutive ox x 2 oy (stride 32): 8 independent gathers in
// flight, 2 coalesced float4 streaming stores. All index math exact-integer
// except the channel map, which reproduces JAX's fp32 multiply+floor bitwise.

__global__ __launch_bounds__(256)
void FRAMES_VisionTransformer_28166395527587_kernel(const float* __restrict__ in,
                                                    float* __restrict__ out) {
    unsigned t = blockIdx.x * blockDim.x + threadIdx.x;   // 2^21 threads
    unsigned ox0 = (t & 15u) << 2;       // 4 consecutive ox
    unsigned oy0 = (t >> 4) & 31u;       // oy0 and oy0+32
    unsigned oz  = (t >> 9) & 63u;
    unsigned b   = t >> 15;

    // Exact integer forms of the fp32 nearest-index maps (exact in fp32)
    unsigned z = (oz * 9u) >> 2;                       // floor(oz*2.25)
    unsigned n  = z / 9u;   unsigned c0 = z - n * 9u;

    const size_t tok_base = (size_t)b * (3137u * 768u)
                          + (size_t)(1u + n * 196u) * 768u;

    // float32(768.0/729.0): correctly-rounded; fp32 mul + floor matches JAX bit-exactly
    const float SC = (float)(768.0 / 729.0);

    // Per-ox (g2, c2) for the 4 consecutive ox
    unsigned g2[4], c2[4];
    #pragma unroll
    for (int i = 0; i < 4; ++i) {
        unsigned x = ((ox0 + (unsigned)i) * 63u) >> 5;  // floor(ox*1.96875)
        g2[i] = x / 9u;
        c2[i] = x - g2[i] * 9u;
    }

    float v[2][4];
    #pragma unroll
    for (int j = 0; j < 2; ++j) {
        unsigned oy = oy0 + 32u * (unsigned)j;
        unsigned y  = (oy * 63u) >> 5;                  // floor(oy*1.96875)
        unsigned g1 = y / 9u;  unsigned c1 = y - g1 * 9u;
        unsigned cb = c0 * 81u + c1 * 9u;
        const float* row = in + tok_base + (size_t)(g1 * 14u) * 768u;
        #pragma unroll
        for (int i = 0; i < 4; ++i) {
            unsigned ch = (unsigned)__float2int_rd((float)(cb + c2[i]) * SC);
            v[j][i] = __ldcs(&row[(size_t)g2[i] * 768u + ch]);
        }
    }

    size_t out_q = ((((size_t)b * 64u + oz) * 64u + oy0) * 64u + ox0) >> 2;
    float4* o4 = reinterpret_cast<float4*>(out);
    __stcs(&o4[out_q],                    make_float4(v[0][0], v[0][1], v[0][2], v[0][3]));
    __stcs(&o4[out_q + (32u * 64u >> 2)], make_float4(v[1][0], v[1][1], v[1][2], v[1][3]));
}

extern "C" void kernel_launch(void* const* d_in, const int* in_sizes, int n_in,
                              void* d_out, int out_size) {
    const float* in = (const float*)d_in[0];
    float* out = (float*)d_out;
    const unsigned n_threads = 16777216u / 8u;    // 2,097,152 (8 outputs/thread)
    const unsigned block = 256u;
    const unsigned grid = n_threads / block;      // 8,192
    FRAMES_VisionTransformer_28166395527587_kernel<<<grid, block>>>(in, out);
}

// round 9
// speedup vs baseline: 1.0060x; 1.0060x over previous
#include <cuda_runtime.h>

// out[b, oz, oy, ox] = in[b*3137*768 + (1 + n*196 + g1*14 + g2)*768 + ch]
//   z = floor(oz*9/4)   -> n = z/9, c0 = z%9
//   y = floor(oy*63/32) -> g1 = y/9, c1 = y%9
//   x = floor(ox*63/32) -> g2 = x/9, c2 = x%9
//   ch = floor(float32(c0*81 + c1*9 + c2) * float32(768.0/729.0))  (bit-exact JAX)
//
// Floor configuration (established over R1-R7): direct gather, warp = 32
// consecutive ox (gather clusters into ~7 tokens x ~2 sectors per LDG),
// thread = 4 oy values (stride 16) for MLP=4, 4 fully-coalesced scalar
// streaming stores. ~380 MB irreducible traffic @ ~6.5 TB/s => ~57-59us.

__global__ __launch_bounds__(512)
void FRAMES_VisionTransformer_28166395527587_kernel(const float* __restrict__ in,
                                                    float* __restrict__ out) {
    unsigned t = blockIdx.x * blockDim.x + threadIdx.x;   // 2^22 threads
    unsigned ox  = t & 63u;
    unsigned oy0 = (t >> 6) & 15u;       // thread covers oy0 + 16k, k=0..3
    unsigned oz  = (t >> 10) & 63u;
    unsigned b   = t >> 16;

    // Exact integer forms of the fp32 nearest-index maps (exact in fp32)
    unsigned z = (oz * 9u) >> 2;                       // floor(oz*2.25)
    unsigned n  = z / 9u;   unsigned c0 = z - n * 9u;
    unsigned x = (ox * 63u) >> 5;                      // floor(ox*1.96875)
    unsigned g2 = x / 9u;   unsigned c2 = x - g2 * 9u;

    const size_t row_base = (size_t)b * (3137u * 768u)
                          + (size_t)(1u + n * 196u + g2) * 768u;
    const unsigned cbase = c0 * 81u + c2;

    // float32(768.0/729.0): correctly-rounded; fp32 mul + floor matches JAX bit-exactly
    const float SC = (float)(768.0 / 729.0);

    float v[4];
    #pragma unroll
    for (int k = 0; k < 4; ++k) {
        unsigned oy = oy0 + 16u * (unsigned)k;
        unsigned y  = (oy * 63u) >> 5;                 // floor(oy*1.96875)
        unsigned g1 = y / 9u;  unsigned c1 = y - g1 * 9u;
        unsigned ch = (unsigned)__float2int_rd((float)(cbase + c1 * 9u) * SC);
        v[k] = __ldcs(&in[row_base + (size_t)(g1 * 14u) * 768u + ch]);
    }

    size_t out_base = (((size_t)b * 64u + oz) * 64u + oy0) * 64u + ox;
    #pragma unroll
    for (int k = 0; k < 4; ++k)
        __stcs(&out[out_base + (size_t)k * (16u * 64u)], v[k]);
}

extern "C" void kernel_launch(void* const* d_in, const int* in_sizes, int n_in,
                              void* d_out, int out_size) {
    const float* in = (const float*)d_in[0];
    float* out = (float*)d_out;
    const unsigned n_threads = 16777216u / 4u;    // 4,194,304 (4 outputs/thread)
    const unsigned block = 512u;
    const unsigned grid = n_threads / block;      // 8,192
    FRAMES_VisionTransformer_28166395527587_kernel<<<grid, block>>>(in, out);
}